// round 14
// baseline (speedup 1.0000x reference)
#include <cuda_runtime.h>
#include <cstdint>

// ============================================================================
// y = ifft2(fft2(x) * sqrt_lambda), ortho. x: (16,768,64,64) f32.
// Pack 2 images as one complex field (filter real & symmetric => exact).
// PERSISTENT 64-thr CTAs, 4/SM: 32KB TMA landing plane (consumed entirely in
// phase 1 -> next pair's TMA issued EARLY, overlapping ~85% of pair latency)
// + separate 16KB float scratch for the two transposes (re/im half-passes,
// rotation swizzle, conflict-free). Packed f32x2 butterflies, imm twiddles.
// ============================================================================

#define NPIX 4096
#define NPAIR 6144          // 12288 images / 2
#define GRID 592            // 148 SMs * 4 CTAs
#define PAIR_BYTES 32768
#define SMEM_BYTES (PAIR_BYTES + NPIX * 4)   // 32KB landing + 16KB scratch

typedef unsigned long long u64c;

__device__ float g_perm[NPIX];   // filter, permuted: g_perm[r*64 + q] = f[r][swap(q)]

// ---- packed f32x2 primitives -----------------------------------------------
__device__ __forceinline__ u64c PADD(u64c a, u64c b) {
    u64c d; asm("add.rn.f32x2 %0,%1,%2;" : "=l"(d) : "l"(a), "l"(b)); return d;
}
__device__ __forceinline__ u64c PSUB(u64c a, u64c b) {
    u64c d; asm("sub.rn.f32x2 %0,%1,%2;" : "=l"(d) : "l"(a), "l"(b)); return d;
}
__device__ __forceinline__ u64c PMUL(u64c a, u64c b) {
    u64c d; asm("mul.rn.f32x2 %0,%1,%2;" : "=l"(d) : "l"(a), "l"(b)); return d;
}
__device__ __forceinline__ u64c PFMA(u64c a, u64c b, u64c c) {
    u64c d; asm("fma.rn.f32x2 %0,%1,%2,%3;" : "=l"(d) : "l"(a), "l"(b), "l"(c)); return d;
}
__device__ __forceinline__ float PLO(u64c v) { return __uint_as_float((unsigned)v); }
__device__ __forceinline__ float PHI(u64c v) { return __uint_as_float((unsigned)(v >> 32)); }
__device__ __forceinline__ u64c PPK(float x, float y) {
    return ((u64c)__float_as_uint(y) << 32) | (u64c)__float_as_uint(x);
}
__device__ __forceinline__ u64c PSWAP(u64c v) { return (v >> 32) | (v << 32); }

// packed sign constants
#define P1M1  0xBF8000003F800000ULL   // ( 1, -1)
#define M1P1  0x3F800000BF800000ULL   // (-1,  1)
#define CCp   0x3F3504F33F3504F3ULL   // ( C,  C)
#define CMCp  0xBF3504F33F3504F3ULL   // ( C, -C)
#define MCCp  0x3F3504F3BF3504F3ULL   // (-C,  C)
#define MCMCp 0xBF3504F3BF3504F3ULL   // (-C, -C)

// ---- compile-time twiddle tables: cos/sin(pi*k/32), k = 0..49 --------------
__device__ constexpr float COS_T[50] = {
    1.000000000f, 0.995184727f, 0.980785280f, 0.956940336f, 0.923879533f,
    0.881921264f, 0.831469612f, 0.773010453f, 0.707106781f, 0.634393284f,
    0.555570233f, 0.471396737f, 0.382683432f, 0.290284677f, 0.195090322f,
    0.098017140f, 0.000000000f,-0.098017140f,-0.195090322f,-0.290284677f,
   -0.382683432f,-0.471396737f,-0.555570233f,-0.634393284f,-0.707106781f,
   -0.773010453f,-0.831469612f,-0.881921264f,-0.923879533f,-0.956940336f,
   -0.980785280f,-0.995184727f,-1.000000000f,-0.995184727f,-0.980785280f,
   -0.956940336f,-0.923879533f,-0.881921264f,-0.831469612f,-0.773010453f,
   -0.707106781f,-0.634393284f,-0.555570233f,-0.471396737f,-0.382683432f,
   -0.290284677f,-0.195090322f,-0.098017140f, 0.000000000f, 0.098017140f };
__device__ constexpr float SIN_T[50] = {
    0.000000000f, 0.098017140f, 0.195090322f, 0.290284677f, 0.382683432f,
    0.471396737f, 0.555570233f, 0.634393284f, 0.707106781f, 0.773010453f,
    0.831469612f, 0.881921264f, 0.923879533f, 0.956940336f, 0.980785280f,
    0.995184727f, 1.000000000f, 0.995184727f, 0.980785280f, 0.956940336f,
    0.923879533f, 0.881921264f, 0.831469612f, 0.773010453f, 0.707106781f,
    0.634393284f, 0.555570233f, 0.471396737f, 0.382683432f, 0.290284677f,
    0.195090322f, 0.098017140f, 0.000000000f,-0.098017140f,-0.195090322f,
   -0.290284677f,-0.382683432f,-0.471396737f,-0.555570233f,-0.634393284f,
   -0.707106781f,-0.773010453f,-0.831469612f,-0.881921264f,-0.923879533f,
   -0.956940336f,-0.980785280f,-0.995184727f,-1.000000000f,-0.995184727f };

// multiply by W64^k (fwd: e^{-i pi k/32}; INV: conjugate). k compile-time.
template <bool INV>
__device__ __forceinline__ u64c ctw(u64c v, int k) {
    const float wx = COS_T[k];
    const float wy = INV ? SIN_T[k] : -SIN_T[k];
    float x = PLO(v), y = PHI(v);
    float rx = fmaf(x, wx, -(y * wy));
    float ry = fmaf(x, wy, y * wx);
    return PPK(rx, ry);
}

// ---- packed radix-8 butterfly (natural order in/out) -----------------------
template <bool INV>
__device__ __forceinline__ void fft8p(u64c* a) {
    const u64c Ka = INV ? M1P1 : P1M1;
    const u64c Kb = INV ? P1M1 : M1P1;
    const u64c Kt = INV ? MCCp : CMCp;
    u64c e0 = a[0], o0 = a[1], e1 = a[2], o1 = a[3];
    u64c e2 = a[4], o2 = a[5], e3 = a[6], o3 = a[7];
    u64c t0 = PADD(e0, e2), t1 = PSUB(e0, e2);
    u64c t2 = PADD(e1, e3), u  = PSUB(e1, e3);
    u64c su = PSWAP(u);
    u64c E0 = PADD(t0, t2), E2 = PSUB(t0, t2);
    u64c E1 = PFMA(su, Ka, t1), E3 = PFMA(su, Kb, t1);
    u64c p0 = PADD(o0, o2), p1 = PSUB(o0, o2);
    u64c p2 = PADD(o1, o3), q  = PSUB(o1, o3);
    u64c sq = PSWAP(q);
    u64c O0 = PADD(p0, p2), O2 = PSUB(p0, p2);
    u64c O1 = PFMA(sq, Ka, p1), O3 = PFMA(sq, Kb, p1);
    u64c s1 = PSWAP(O1);
    O1 = PFMA(O1, CCp,   PMUL(s1, Kt));
    u64c s3 = PSWAP(O3);
    O3 = PFMA(O3, MCMCp, PMUL(s3, Kt));
    u64c s2 = PSWAP(O2);
    a[0] = PADD(E0, O0); a[4] = PSUB(E0, O0);
    a[1] = PADD(E1, O1); a[5] = PSUB(E1, O1);
    a[2] = PFMA(s2, Ka, E2); a[6] = PFMA(s2, Kb, E2);
    a[3] = PADD(E3, O3); a[7] = PSUB(E3, O3);
}

// 64-pt FFT, natural input. Output digit-swapped: freq (c+8d) at slot (8c+d).
template <bool INV>
__device__ __forceinline__ void fft64_nat(u64c* v) {
    #pragma unroll
    for (int b = 0; b < 8; b++) {
        u64c a[8];
        #pragma unroll
        for (int j = 0; j < 8; j++) a[j] = v[b + 8 * j];
        fft8p<INV>(a);
        #pragma unroll
        for (int j = 0; j < 8; j++) v[b + 8 * j] = a[j];
    }
    #pragma unroll
    for (int b = 1; b < 8; b++)
        #pragma unroll
        for (int c = 1; c < 8; c++)
            v[8 * c + b] = ctw<INV>(v[8 * c + b], b * c);
    #pragma unroll
    for (int c = 0; c < 8; c++) fft8p<INV>(v + 8 * c);
}

// 64-pt FFT, digit-swapped input, natural output.
template <bool INV>
__device__ __forceinline__ void fft64_swapin(u64c* v) {
    #pragma unroll
    for (int c = 0; c < 8; c++) fft8p<INV>(v + 8 * c);
    #pragma unroll
    for (int c = 1; c < 8; c++)
        #pragma unroll
        for (int e = 1; e < 8; e++)
            v[8 * c + e] = ctw<INV>(v[8 * c + e], c * e);
    #pragma unroll
    for (int e = 0; e < 8; e++) {
        u64c a[8];
        #pragma unroll
        for (int cc = 0; cc < 8; cc++) a[cc] = v[8 * cc + e];
        fft8p<INV>(a);
        #pragma unroll
        for (int f = 0; f < 8; f++) v[e + 8 * f] = a[f];
    }
}

// ============================================================================
// Filter build (tiny, one block).
// ============================================================================
__global__ void build_filter_kernel(const float* __restrict__ g1p,
                                    const float* __restrict__ raw_deltas,
                                    const int* __restrict__ bin_idx) {
    __shared__ float gbin[16];
    __shared__ float red[256];
    int tid = threadIdx.x;

    if (tid == 0) {
        float acc = g1p[0];
        gbin[0] = acc;
        #pragma unroll
        for (int i = 0; i < 15; i++) {
            float v = raw_deltas[i];
            float sp = (v > 20.0f) ? v : log1pf(expf(v));
            acc += sp;
            gbin[i + 1] = acc;
        }
    }
    __syncthreads();

    float ell[16];
    float s = 0.0f;
    #pragma unroll
    for (int i = 0; i < 16; i++) {
        int p = tid + 256 * i;
        ell[i] = gbin[bin_idx[p]];
        s += ell[i];
    }
    red[tid] = s;
    __syncthreads();
    for (int off = 128; off > 0; off >>= 1) {
        if (tid < off) red[tid] += red[tid + off];
        __syncthreads();
    }
    float m1 = red[0] * (1.0f / 4096.0f);
    __syncthreads();

    float s2 = 0.0f;
    #pragma unroll
    for (int i = 0; i < 16; i++) {
        float e = ell[i] - m1;
        e = fminf(3.0f, fmaxf(-3.0f, e));
        ell[i] = e;
        s2 += e;
    }
    red[tid] = s2;
    __syncthreads();
    for (int off = 128; off > 0; off >>= 1) {
        if (tid < off) red[tid] += red[tid + off];
        __syncthreads();
    }
    float m2 = red[0] * (1.0f / 4096.0f);

    #pragma unroll
    for (int i = 0; i < 16; i++) {
        int p = tid + 256 * i;              // p = r*64 + j
        float val = expf(0.5f * (ell[i] - m2)) * (1.0f / 4096.0f);
        int j = p & 63;
        int q = ((j & 7) << 3) | (j >> 3);  // swap(j)
        g_perm[(p & ~63) | q] = val;
    }
}

// ============================================================================
// Main kernel: persistent, 64 threads, 4 CTAs/SM.
// smem: L = 32KB TMA landing (pair input), T = 16KB float transpose scratch.
// ============================================================================
__global__ void __launch_bounds__(64, 6)
spectral_kernel(const float* __restrict__ x, float* __restrict__ y) {
    extern __shared__ __align__(16) float SM[];   // [0,8192): L, [8192,12288): T
    __shared__ __align__(8) unsigned long long mbar;

    const int c = threadIdx.x;
    float* L = SM;
    float* T = SM + 2 * NPIX;

    uint32_t l_u32, mb_u32;
    {
        uint64_t t;
        asm("cvta.to.shared.u64 %0, %1;" : "=l"(t) : "l"((void*)L));     l_u32 = (uint32_t)t;
        asm("cvta.to.shared.u64 %0, %1;" : "=l"(t) : "l"((void*)&mbar)); mb_u32 = (uint32_t)t;
    }

    if (c == 0)
        asm volatile("mbarrier.init.shared.b64 [%0], 1;" :: "r"(mb_u32) : "memory");
    __syncthreads();

    if (c == 0) {
        asm volatile("mbarrier.arrive.expect_tx.shared.b64 _, [%0], %1;"
                     :: "r"(mb_u32), "r"(PAIR_BYTES) : "memory");
        asm volatile("cp.async.bulk.shared::cluster.global.mbarrier::complete_tx::bytes [%0], [%1], %2, [%3];"
                     :: "r"(l_u32), "l"(x + (size_t)blockIdx.x * (2 * NPIX)),
                        "r"(PAIR_BYTES), "r"(mb_u32) : "memory");
    }

    int phase = 0;
    for (int p = blockIdx.x; p < NPAIR; p += GRID) {
        // ---- wait for input pair p (acquire)
        {
            uint32_t done;
            do {
                asm volatile("{\n\t.reg .pred q;\n\t"
                             "mbarrier.try_wait.parity.acquire.cta.shared::cta.b64 q, [%1], %2;\n\t"
                             "selp.b32 %0, 1, 0, q;\n\t}"
                             : "=r"(done) : "r"(mb_u32), "r"(phase) : "memory");
            } while (!done);
        }
        phase ^= 1;

        u64c v[64];

        // ---- Phase 1: column c of both images (conflict-free LDS)
        #pragma unroll
        for (int i = 0; i < 64; i++)
            v[i] = PPK(L[i * 64 + c], L[NPIX + i * 64 + c]);
        __syncthreads();                 // all input reads done; L reusable

        // ---- EARLY prefetch of next pair into L (overlaps everything below)
        if (c == 0 && p + GRID < NPAIR) {
            asm volatile("fence.proxy.async.shared::cta;" ::: "memory");
            asm volatile("mbarrier.arrive.expect_tx.shared.b64 _, [%0], %1;"
                         :: "r"(mb_u32), "r"(PAIR_BYTES) : "memory");
            asm volatile("cp.async.bulk.shared::cluster.global.mbarrier::complete_tx::bytes [%0], [%1], %2, [%3];"
                         :: "r"(l_u32), "l"(x + (size_t)(p + GRID) * (2 * NPIX)),
                            "r"(PAIR_BYTES), "r"(mb_u32) : "memory");
        }

        fft64_nat<false>(v);             // fwd column FFT (swapped output)

        // ---- Transpose 1: re pass then im pass through T (rotation swizzle)
        const int r = c;
        #pragma unroll
        for (int m = 0; m < 64; m++) {
            int s = ((m & 7) << 3) | (m >> 3);     // slot holding freq m
            T[m * 64 + ((c + m) & 63)] = PLO(v[s]);
        }
        __syncthreads();
        float nx[64];
        #pragma unroll
        for (int j = 0; j < 64; j++)
            nx[j] = T[r * 64 + ((j + r) & 63)];
        __syncthreads();
        #pragma unroll
        for (int m = 0; m < 64; m++) {
            int s = ((m & 7) << 3) | (m >> 3);
            T[m * 64 + ((c + m) & 63)] = PHI(v[s]);
        }
        __syncthreads();
        #pragma unroll
        for (int j = 0; j < 64; j++)
            v[j] = PPK(nx[j], T[r * 64 + ((j + r) & 63)]);

        // ---- Row phase: fwd FFT + filter + inv FFT (registers)
        fft64_nat<false>(v);
        {
            const float4* F = (const float4*)g_perm;
            #pragma unroll
            for (int k = 0; k < 16; k++) {
                float4 f = __ldg(&F[r * 16 + k]);
                v[4 * k + 0] = PMUL(v[4 * k + 0], PPK(f.x, f.x));
                v[4 * k + 1] = PMUL(v[4 * k + 1], PPK(f.y, f.y));
                v[4 * k + 2] = PMUL(v[4 * k + 2], PPK(f.z, f.z));
                v[4 * k + 3] = PMUL(v[4 * k + 3], PPK(f.w, f.w));
            }
        }
        fft64_swapin<true>(v);           // natural j-order output

        // ---- Transpose 2: re pass then im pass through T
        __syncthreads();                 // T1 loads complete before overwrite
        #pragma unroll
        for (int j = 0; j < 64; j++)
            T[r * 64 + ((j + r) & 63)] = PLO(v[j]);
        __syncthreads();
        #pragma unroll
        for (int m = 0; m < 64; m++)
            nx[m] = T[m * 64 + ((c + m) & 63)];
        __syncthreads();
        #pragma unroll
        for (int j = 0; j < 64; j++)
            T[r * 64 + ((j + r) & 63)] = PHI(v[j]);
        __syncthreads();
        #pragma unroll
        for (int m = 0; m < 64; m++)
            v[m] = PPK(nx[m], T[m * 64 + ((c + m) & 63)]);

        // ---- Inverse column FFT + direct coalesced stores
        fft64_nat<true>(v);

        float* Ya = y + (size_t)p * (2 * NPIX);
        float* Yb = Ya + NPIX;
        #pragma unroll
        for (int i = 0; i < 64; i++) {
            int s = ((i & 7) << 3) | (i >> 3);     // slot holding spatial row i
            Ya[i * 64 + c] = PLO(v[s]);
            Yb[i * 64 + c] = PHI(v[s]);
        }
        __syncthreads();                 // T idle before next-iter reuse
    }
}

extern "C" void kernel_launch(void* const* d_in, const int* in_sizes, int n_in,
                              void* d_out, int out_size) {
    const float* x   = (const float*)d_in[0];
    const float* g1  = (const float*)d_in[1];
    const float* raw = (const float*)d_in[2];
    const int* bidx  = (const int*)d_in[3];
    float* y = (float*)d_out;

    static bool attr_set = false;
    if (!attr_set) {
        cudaFuncSetAttribute(spectral_kernel,
                             cudaFuncAttributeMaxDynamicSharedMemorySize, SMEM_BYTES);
        attr_set = true;
    }

    build_filter_kernel<<<1, 256>>>(g1, raw, bidx);
    spectral_kernel<<<GRID, 64, SMEM_BYTES>>>(x, y);
}

// round 15
// speedup vs baseline: 1.7927x; 1.7927x over previous
#include <cuda_runtime.h>
#include <cstdint>

// ============================================================================
// y = ifft2(fft2(x) * sqrt_lambda), ortho. x: (16,768,64,64) f32.
// Pack 2 images as one complex field (filter real & symmetric => exact).
// PERSISTENT 128-thr CTAs (444 = 3/SM), 2 independent 64-thr groups per CTA,
// each looping over pairs. Per group: direct coalesced LDG/STG, 32KB u64
// rotation-swizzled smem plane for the 2 transposes, named barriers,
// L2 prefetch of the next pair issued mid-pipeline. Packed f32x2 butterflies,
// compile-time immediate twiddles.
// ============================================================================

#define NPIX 4096
#define NPAIR 6144          // 12288 images / 2
#define NITER 3072          // CTA-iterations (2 pairs each)
#define GRID 444            // 148 SMs * 3 CTAs
#define SMEM_BYTES (2 * NPIX * 8)   // 65536 (one 32KB u64 plane per group)

typedef unsigned long long u64c;

__device__ float g_perm[NPIX];   // filter, permuted: g_perm[r*64 + q] = f[r][swap(q)]

// ---- packed f32x2 primitives -----------------------------------------------
__device__ __forceinline__ u64c PADD(u64c a, u64c b) {
    u64c d; asm("add.rn.f32x2 %0,%1,%2;" : "=l"(d) : "l"(a), "l"(b)); return d;
}
__device__ __forceinline__ u64c PSUB(u64c a, u64c b) {
    u64c d; asm("sub.rn.f32x2 %0,%1,%2;" : "=l"(d) : "l"(a), "l"(b)); return d;
}
__device__ __forceinline__ u64c PMUL(u64c a, u64c b) {
    u64c d; asm("mul.rn.f32x2 %0,%1,%2;" : "=l"(d) : "l"(a), "l"(b)); return d;
}
__device__ __forceinline__ u64c PFMA(u64c a, u64c b, u64c c) {
    u64c d; asm("fma.rn.f32x2 %0,%1,%2,%3;" : "=l"(d) : "l"(a), "l"(b), "l"(c)); return d;
}
__device__ __forceinline__ float PLO(u64c v) { return __uint_as_float((unsigned)v); }
__device__ __forceinline__ float PHI(u64c v) { return __uint_as_float((unsigned)(v >> 32)); }
__device__ __forceinline__ u64c PPK(float x, float y) {
    return ((u64c)__float_as_uint(y) << 32) | (u64c)__float_as_uint(x);
}
__device__ __forceinline__ u64c PSWAP(u64c v) { return (v >> 32) | (v << 32); }

// packed sign constants
#define P1M1  0xBF8000003F800000ULL   // ( 1, -1)
#define M1P1  0x3F800000BF800000ULL   // (-1,  1)
#define CCp   0x3F3504F33F3504F3ULL   // ( C,  C)
#define CMCp  0xBF3504F33F3504F3ULL   // ( C, -C)
#define MCCp  0x3F3504F3BF3504F3ULL   // (-C,  C)
#define MCMCp 0xBF3504F3BF3504F3ULL   // (-C, -C)

// ---- compile-time twiddle tables: cos/sin(pi*k/32), k = 0..49 --------------
__device__ constexpr float COS_T[50] = {
    1.000000000f, 0.995184727f, 0.980785280f, 0.956940336f, 0.923879533f,
    0.881921264f, 0.831469612f, 0.773010453f, 0.707106781f, 0.634393284f,
    0.555570233f, 0.471396737f, 0.382683432f, 0.290284677f, 0.195090322f,
    0.098017140f, 0.000000000f,-0.098017140f,-0.195090322f,-0.290284677f,
   -0.382683432f,-0.471396737f,-0.555570233f,-0.634393284f,-0.707106781f,
   -0.773010453f,-0.831469612f,-0.881921264f,-0.923879533f,-0.956940336f,
   -0.980785280f,-0.995184727f,-1.000000000f,-0.995184727f,-0.980785280f,
   -0.956940336f,-0.923879533f,-0.881921264f,-0.831469612f,-0.773010453f,
   -0.707106781f,-0.634393284f,-0.555570233f,-0.471396737f,-0.382683432f,
   -0.290284677f,-0.195090322f,-0.098017140f, 0.000000000f, 0.098017140f };
__device__ constexpr float SIN_T[50] = {
    0.000000000f, 0.098017140f, 0.195090322f, 0.290284677f, 0.382683432f,
    0.471396737f, 0.555570233f, 0.634393284f, 0.707106781f, 0.773010453f,
    0.831469612f, 0.881921264f, 0.923879533f, 0.956940336f, 0.980785280f,
    0.995184727f, 1.000000000f, 0.995184727f, 0.980785280f, 0.956940336f,
    0.923879533f, 0.881921264f, 0.831469612f, 0.773010453f, 0.707106781f,
    0.634393284f, 0.555570233f, 0.471396737f, 0.382683432f, 0.290284677f,
    0.195090322f, 0.098017140f, 0.000000000f,-0.098017140f,-0.195090322f,
   -0.290284677f,-0.382683432f,-0.471396737f,-0.555570233f,-0.634393284f,
   -0.707106781f,-0.773010453f,-0.831469612f,-0.881921264f,-0.923879533f,
   -0.956940336f,-0.980785280f,-0.995184727f,-1.000000000f,-0.995184727f };

// multiply by W64^k (fwd: e^{-i pi k/32}; INV: conjugate). k compile-time.
template <bool INV>
__device__ __forceinline__ u64c ctw(u64c v, int k) {
    const float wx = COS_T[k];
    const float wy = INV ? SIN_T[k] : -SIN_T[k];
    float x = PLO(v), y = PHI(v);
    float rx = fmaf(x, wx, -(y * wy));
    float ry = fmaf(x, wy, y * wx);
    return PPK(rx, ry);
}

// ---- packed radix-8 butterfly (natural order in/out) -----------------------
template <bool INV>
__device__ __forceinline__ void fft8p(u64c* a) {
    const u64c Ka = INV ? M1P1 : P1M1;
    const u64c Kb = INV ? P1M1 : M1P1;
    const u64c Kt = INV ? MCCp : CMCp;
    u64c e0 = a[0], o0 = a[1], e1 = a[2], o1 = a[3];
    u64c e2 = a[4], o2 = a[5], e3 = a[6], o3 = a[7];
    u64c t0 = PADD(e0, e2), t1 = PSUB(e0, e2);
    u64c t2 = PADD(e1, e3), u  = PSUB(e1, e3);
    u64c su = PSWAP(u);
    u64c E0 = PADD(t0, t2), E2 = PSUB(t0, t2);
    u64c E1 = PFMA(su, Ka, t1), E3 = PFMA(su, Kb, t1);
    u64c p0 = PADD(o0, o2), p1 = PSUB(o0, o2);
    u64c p2 = PADD(o1, o3), q  = PSUB(o1, o3);
    u64c sq = PSWAP(q);
    u64c O0 = PADD(p0, p2), O2 = PSUB(p0, p2);
    u64c O1 = PFMA(sq, Ka, p1), O3 = PFMA(sq, Kb, p1);
    u64c s1 = PSWAP(O1);
    O1 = PFMA(O1, CCp,   PMUL(s1, Kt));
    u64c s3 = PSWAP(O3);
    O3 = PFMA(O3, MCMCp, PMUL(s3, Kt));
    u64c s2 = PSWAP(O2);
    a[0] = PADD(E0, O0); a[4] = PSUB(E0, O0);
    a[1] = PADD(E1, O1); a[5] = PSUB(E1, O1);
    a[2] = PFMA(s2, Ka, E2); a[6] = PFMA(s2, Kb, E2);
    a[3] = PADD(E3, O3); a[7] = PSUB(E3, O3);
}

// 64-pt FFT, natural input. Output digit-swapped: freq (c+8d) at slot (8c+d).
template <bool INV>
__device__ __forceinline__ void fft64_nat(u64c* v) {
    #pragma unroll
    for (int b = 0; b < 8; b++) {
        u64c a[8];
        #pragma unroll
        for (int j = 0; j < 8; j++) a[j] = v[b + 8 * j];
        fft8p<INV>(a);
        #pragma unroll
        for (int j = 0; j < 8; j++) v[b + 8 * j] = a[j];
    }
    #pragma unroll
    for (int b = 1; b < 8; b++)
        #pragma unroll
        for (int c = 1; c < 8; c++)
            v[8 * c + b] = ctw<INV>(v[8 * c + b], b * c);
    #pragma unroll
    for (int c = 0; c < 8; c++) fft8p<INV>(v + 8 * c);
}

// 64-pt FFT, digit-swapped input, natural output.
template <bool INV>
__device__ __forceinline__ void fft64_swapin(u64c* v) {
    #pragma unroll
    for (int c = 0; c < 8; c++) fft8p<INV>(v + 8 * c);
    #pragma unroll
    for (int c = 1; c < 8; c++)
        #pragma unroll
        for (int e = 1; e < 8; e++)
            v[8 * c + e] = ctw<INV>(v[8 * c + e], c * e);
    #pragma unroll
    for (int e = 0; e < 8; e++) {
        u64c a[8];
        #pragma unroll
        for (int cc = 0; cc < 8; cc++) a[cc] = v[8 * cc + e];
        fft8p<INV>(a);
        #pragma unroll
        for (int f = 0; f < 8; f++) v[e + 8 * f] = a[f];
    }
}

// ============================================================================
// Filter build (tiny, one block).
// ============================================================================
__global__ void build_filter_kernel(const float* __restrict__ g1p,
                                    const float* __restrict__ raw_deltas,
                                    const int* __restrict__ bin_idx) {
    __shared__ float gbin[16];
    __shared__ float red[256];
    int tid = threadIdx.x;

    if (tid == 0) {
        float acc = g1p[0];
        gbin[0] = acc;
        #pragma unroll
        for (int i = 0; i < 15; i++) {
            float v = raw_deltas[i];
            float sp = (v > 20.0f) ? v : log1pf(expf(v));
            acc += sp;
            gbin[i + 1] = acc;
        }
    }
    __syncthreads();

    float ell[16];
    float s = 0.0f;
    #pragma unroll
    for (int i = 0; i < 16; i++) {
        int p = tid + 256 * i;
        ell[i] = gbin[bin_idx[p]];
        s += ell[i];
    }
    red[tid] = s;
    __syncthreads();
    for (int off = 128; off > 0; off >>= 1) {
        if (tid < off) red[tid] += red[tid + off];
        __syncthreads();
    }
    float m1 = red[0] * (1.0f / 4096.0f);
    __syncthreads();

    float s2 = 0.0f;
    #pragma unroll
    for (int i = 0; i < 16; i++) {
        float e = ell[i] - m1;
        e = fminf(3.0f, fmaxf(-3.0f, e));
        ell[i] = e;
        s2 += e;
    }
    red[tid] = s2;
    __syncthreads();
    for (int off = 128; off > 0; off >>= 1) {
        if (tid < off) red[tid] += red[tid + off];
        __syncthreads();
    }
    float m2 = red[0] * (1.0f / 4096.0f);

    #pragma unroll
    for (int i = 0; i < 16; i++) {
        int p = tid + 256 * i;              // p = r*64 + j
        float val = expf(0.5f * (ell[i] - m2)) * (1.0f / 4096.0f);
        int j = p & 63;
        int q = ((j & 7) << 3) | (j >> 3);  // swap(j)
        g_perm[(p & ~63) | q] = val;
    }
}

// ============================================================================
// Main kernel: persistent, 128 threads = 2 groups x 64; group g loops over
// pairs 2*(blockIdx + k*GRID) + g with its own 32KB u64 plane + named barrier.
// ============================================================================
__global__ void __launch_bounds__(128, 3)
spectral_kernel(const float* __restrict__ x, float* __restrict__ y) {
    extern __shared__ u64c S[];          // 2 * NPIX u64 = 64KB

    const int tid = threadIdx.x;
    const int g = tid >> 6;              // group 0/1 (warps {0,1} / {2,3})
    const int c = tid & 63;
    u64c* Sg = S + g * NPIX;
    const int barid = g + 1;
    const int r = c;                     // row owned in the row phase

    for (int base = blockIdx.x; base < NITER; base += GRID) {
        const int p = 2 * base + g;
        const size_t off = (size_t)p * (2 * NPIX);
        const float* A = x + off;
        const float* B = A + NPIX;

        u64c v[64];

        // ---- Phase 1: column c of both images (coalesced LDG)
        #pragma unroll
        for (int i = 0; i < 64; i++)
            v[i] = PPK(A[i * 64 + c], B[i * 64 + c]);

        // Forward column FFT (output slot q holds freq swap(q)).
        fft64_nat<false>(v);

        // ---- Transpose 1 (u64): column layout -> row layout.
        #pragma unroll
        for (int m = 0; m < 64; m++) {
            int s = ((m & 7) << 3) | (m >> 3);       // slot holding freq m
            Sg[m * 64 + ((c + m) & 63)] = v[s];
        }
        asm volatile("bar.sync %0, 64;" :: "r"(barid) : "memory");
        #pragma unroll
        for (int j = 0; j < 64; j++)
            v[j] = Sg[r * 64 + ((j + r) & 63)];      // own row only

        // ---- L2 prefetch of this group's NEXT pair (used ~10K cyc later)
        {
            int pn = 2 * (base + GRID) + g;
            if (pn < NPAIR) {
                const char* nb = (const char*)(x + (size_t)pn * (2 * NPIX));
                #pragma unroll
                for (int q2 = 0; q2 < 4; q2++)
                    asm volatile("prefetch.global.L2 [%0];"
                                 :: "l"(nb + ((size_t)(q2 * 64 + c) << 7)));
            }
        }

        // ---- Row phase: fwd row FFT + filter + inv row FFT (registers).
        fft64_nat<false>(v);
        {
            const float4* F = (const float4*)g_perm;
            #pragma unroll
            for (int k = 0; k < 16; k++) {
                float4 f = __ldg(&F[r * 16 + k]);
                v[4 * k + 0] = PMUL(v[4 * k + 0], PPK(f.x, f.x));
                v[4 * k + 1] = PMUL(v[4 * k + 1], PPK(f.y, f.y));
                v[4 * k + 2] = PMUL(v[4 * k + 2], PPK(f.z, f.z));
                v[4 * k + 3] = PMUL(v[4 * k + 3], PPK(f.w, f.w));
            }
        }
        fft64_swapin<true>(v);   // natural j-order output

        // ---- Transpose 2 (u64): row -> column. T1-load and this store touch
        // only the thread's OWN row -> no barrier needed before the store.
        #pragma unroll
        for (int j = 0; j < 64; j++)
            Sg[r * 64 + ((j + r) & 63)] = v[j];
        asm volatile("bar.sync %0, 64;" :: "r"(barid) : "memory");
        #pragma unroll
        for (int m = 0; m < 64; m++)
            v[m] = Sg[m * 64 + ((c + m) & 63)];
        // barrier AFTER the cross-thread T2 loads, before next-iter T1 store:
        asm volatile("bar.sync %0, 64;" :: "r"(barid) : "memory");

        // ---- Inverse column FFT + direct coalesced stores.
        fft64_nat<true>(v);

        float* Ya = y + off;
        float* Yb = Ya + NPIX;
        #pragma unroll
        for (int i = 0; i < 64; i++) {
            int s = ((i & 7) << 3) | (i >> 3);       // slot holding spatial row i
            Ya[i * 64 + c] = PLO(v[s]);
            Yb[i * 64 + c] = PHI(v[s]);
        }
    }
}

extern "C" void kernel_launch(void* const* d_in, const int* in_sizes, int n_in,
                              void* d_out, int out_size) {
    const float* x   = (const float*)d_in[0];
    const float* g1  = (const float*)d_in[1];
    const float* raw = (const float*)d_in[2];
    const int* bidx  = (const int*)d_in[3];
    float* y = (float*)d_out;

    static bool attr_set = false;
    if (!attr_set) {
        cudaFuncSetAttribute(spectral_kernel,
                             cudaFuncAttributeMaxDynamicSharedMemorySize, SMEM_BYTES);
        attr_set = true;
    }

    build_filter_kernel<<<1, 256>>>(g1, raw, bidx);
    spectral_kernel<<<GRID, 128, SMEM_BYTES>>>(x, y);
}

// round 17
// speedup vs baseline: 1.8585x; 1.0367x over previous
#include <cuda_runtime.h>
#include <cstdint>

// ============================================================================
// y = ifft2(fft2(x) * sqrt_lambda), ortho. x: (16,768,64,64) f32.
// Pack 2 images as one complex field (filter real & symmetric => exact).
// 128-thread CTAs, 2 independent 64-thread groups (one pair each, own 32KB
// u64 rotation-swizzled smem plane, own named barrier -> 2 barriers/pair).
// Packed f32x2 butterflies, compile-time immediate twiddles. Streaming
// cache hints (.cs) on the once-touched global traffic.
// ============================================================================

#define NPIX 4096
#define NPAIR 6144          // 12288 images / 2
#define GRID 3072           // 2 pairs per CTA
#define SMEM_BYTES (2 * NPIX * 8)   // 65536

typedef unsigned long long u64c;

__device__ float g_perm[NPIX];   // filter, permuted: g_perm[r*64 + q] = f[r][swap(q)]

// ---- packed f32x2 primitives -----------------------------------------------
__device__ __forceinline__ u64c PADD(u64c a, u64c b) {
    u64c d; asm("add.rn.f32x2 %0,%1,%2;" : "=l"(d) : "l"(a), "l"(b)); return d;
}
__device__ __forceinline__ u64c PSUB(u64c a, u64c b) {
    u64c d; asm("sub.rn.f32x2 %0,%1,%2;" : "=l"(d) : "l"(a), "l"(b)); return d;
}
__device__ __forceinline__ u64c PMUL(u64c a, u64c b) {
    u64c d; asm("mul.rn.f32x2 %0,%1,%2;" : "=l"(d) : "l"(a), "l"(b)); return d;
}
__device__ __forceinline__ u64c PFMA(u64c a, u64c b, u64c c) {
    u64c d; asm("fma.rn.f32x2 %0,%1,%2,%3;" : "=l"(d) : "l"(a), "l"(b), "l"(c)); return d;
}
__device__ __forceinline__ float PLO(u64c v) { return __uint_as_float((unsigned)v); }
__device__ __forceinline__ float PHI(u64c v) { return __uint_as_float((unsigned)(v >> 32)); }
__device__ __forceinline__ u64c PPK(float x, float y) {
    return ((u64c)__float_as_uint(y) << 32) | (u64c)__float_as_uint(x);
}
__device__ __forceinline__ u64c PSWAP(u64c v) { return (v >> 32) | (v << 32); }

// packed sign constants
#define P1M1  0xBF8000003F800000ULL   // ( 1, -1)
#define M1P1  0x3F800000BF800000ULL   // (-1,  1)
#define CCp   0x3F3504F33F3504F3ULL   // ( C,  C)
#define CMCp  0xBF3504F33F3504F3ULL   // ( C, -C)
#define MCCp  0x3F3504F3BF3504F3ULL   // (-C,  C)
#define MCMCp 0xBF3504F3BF3504F3ULL   // (-C, -C)

// ---- compile-time twiddle tables: cos/sin(pi*k/32), k = 0..49 --------------
__device__ constexpr float COS_T[50] = {
    1.000000000f, 0.995184727f, 0.980785280f, 0.956940336f, 0.923879533f,
    0.881921264f, 0.831469612f, 0.773010453f, 0.707106781f, 0.634393284f,
    0.555570233f, 0.471396737f, 0.382683432f, 0.290284677f, 0.195090322f,
    0.098017140f, 0.000000000f,-0.098017140f,-0.195090322f,-0.290284677f,
   -0.382683432f,-0.471396737f,-0.555570233f,-0.634393284f,-0.707106781f,
   -0.773010453f,-0.831469612f,-0.881921264f,-0.923879533f,-0.956940336f,
   -0.980785280f,-0.995184727f,-1.000000000f,-0.995184727f,-0.980785280f,
   -0.956940336f,-0.923879533f,-0.881921264f,-0.831469612f,-0.773010453f,
   -0.707106781f,-0.634393284f,-0.555570233f,-0.471396737f,-0.382683432f,
   -0.290284677f,-0.195090322f,-0.098017140f, 0.000000000f, 0.098017140f };
__device__ constexpr float SIN_T[50] = {
    0.000000000f, 0.098017140f, 0.195090322f, 0.290284677f, 0.382683432f,
    0.471396737f, 0.555570233f, 0.634393284f, 0.707106781f, 0.773010453f,
    0.831469612f, 0.881921264f, 0.923879533f, 0.956940336f, 0.980785280f,
    0.995184727f, 1.000000000f, 0.995184727f, 0.980785280f, 0.956940336f,
    0.923879533f, 0.881921264f, 0.831469612f, 0.773010453f, 0.707106781f,
    0.634393284f, 0.555570233f, 0.471396737f, 0.382683432f, 0.290284677f,
    0.195090322f, 0.098017140f, 0.000000000f,-0.098017140f,-0.195090322f,
   -0.290284677f,-0.382683432f,-0.471396737f,-0.555570233f,-0.634393284f,
   -0.707106781f,-0.773010453f,-0.831469612f,-0.881921264f,-0.923879533f,
   -0.956940336f,-0.980785280f,-0.995184727f,-1.000000000f,-0.995184727f };

// multiply by W64^k (fwd: e^{-i pi k/32}; INV: conjugate). k compile-time.
template <bool INV>
__device__ __forceinline__ u64c ctw(u64c v, int k) {
    const float wx = COS_T[k];
    const float wy = INV ? SIN_T[k] : -SIN_T[k];
    float x = PLO(v), y = PHI(v);
    float rx = fmaf(x, wx, -(y * wy));
    float ry = fmaf(x, wy, y * wx);
    return PPK(rx, ry);
}

// ---- packed radix-8 butterfly (natural order in/out) -----------------------
template <bool INV>
__device__ __forceinline__ void fft8p(u64c* a) {
    const u64c Ka = INV ? M1P1 : P1M1;
    const u64c Kb = INV ? P1M1 : M1P1;
    const u64c Kt = INV ? MCCp : CMCp;
    u64c e0 = a[0], o0 = a[1], e1 = a[2], o1 = a[3];
    u64c e2 = a[4], o2 = a[5], e3 = a[6], o3 = a[7];
    u64c t0 = PADD(e0, e2), t1 = PSUB(e0, e2);
    u64c t2 = PADD(e1, e3), u  = PSUB(e1, e3);
    u64c su = PSWAP(u);
    u64c E0 = PADD(t0, t2), E2 = PSUB(t0, t2);
    u64c E1 = PFMA(su, Ka, t1), E3 = PFMA(su, Kb, t1);
    u64c p0 = PADD(o0, o2), p1 = PSUB(o0, o2);
    u64c p2 = PADD(o1, o3), q  = PSUB(o1, o3);
    u64c sq = PSWAP(q);
    u64c O0 = PADD(p0, p2), O2 = PSUB(p0, p2);
    u64c O1 = PFMA(sq, Ka, p1), O3 = PFMA(sq, Kb, p1);
    u64c s1 = PSWAP(O1);
    O1 = PFMA(O1, CCp,   PMUL(s1, Kt));
    u64c s3 = PSWAP(O3);
    O3 = PFMA(O3, MCMCp, PMUL(s3, Kt));
    u64c s2 = PSWAP(O2);
    a[0] = PADD(E0, O0); a[4] = PSUB(E0, O0);
    a[1] = PADD(E1, O1); a[5] = PSUB(E1, O1);
    a[2] = PFMA(s2, Ka, E2); a[6] = PFMA(s2, Kb, E2);
    a[3] = PADD(E3, O3); a[7] = PSUB(E3, O3);
}

// 64-pt FFT, natural input. Output digit-swapped: freq (c+8d) at slot (8c+d).
template <bool INV>
__device__ __forceinline__ void fft64_nat(u64c* v) {
    #pragma unroll
    for (int b = 0; b < 8; b++) {
        u64c a[8];
        #pragma unroll
        for (int j = 0; j < 8; j++) a[j] = v[b + 8 * j];
        fft8p<INV>(a);
        #pragma unroll
        for (int j = 0; j < 8; j++) v[b + 8 * j] = a[j];
    }
    #pragma unroll
    for (int b = 1; b < 8; b++)
        #pragma unroll
        for (int c = 1; c < 8; c++)
            v[8 * c + b] = ctw<INV>(v[8 * c + b], b * c);
    #pragma unroll
    for (int c = 0; c < 8; c++) fft8p<INV>(v + 8 * c);
}

// 64-pt FFT, digit-swapped input, natural output.
template <bool INV>
__device__ __forceinline__ void fft64_swapin(u64c* v) {
    #pragma unroll
    for (int c = 0; c < 8; c++) fft8p<INV>(v + 8 * c);
    #pragma unroll
    for (int c = 1; c < 8; c++)
        #pragma unroll
        for (int e = 1; e < 8; e++)
            v[8 * c + e] = ctw<INV>(v[8 * c + e], c * e);
    #pragma unroll
    for (int e = 0; e < 8; e++) {
        u64c a[8];
        #pragma unroll
        for (int cc = 0; cc < 8; cc++) a[cc] = v[8 * cc + e];
        fft8p<INV>(a);
        #pragma unroll
        for (int f = 0; f < 8; f++) v[e + 8 * f] = a[f];
    }
}

// ============================================================================
// Filter build (tiny, one block).
// ============================================================================
__global__ void build_filter_kernel(const float* __restrict__ g1p,
                                    const float* __restrict__ raw_deltas,
                                    const int* __restrict__ bin_idx) {
    __shared__ float gbin[16];
    __shared__ float red[256];
    int tid = threadIdx.x;

    if (tid == 0) {
        float acc = g1p[0];
        gbin[0] = acc;
        #pragma unroll
        for (int i = 0; i < 15; i++) {
            float v = raw_deltas[i];
            float sp = (v > 20.0f) ? v : log1pf(expf(v));
            acc += sp;
            gbin[i + 1] = acc;
        }
    }
    __syncthreads();

    float ell[16];
    float s = 0.0f;
    #pragma unroll
    for (int i = 0; i < 16; i++) {
        int p = tid + 256 * i;
        ell[i] = gbin[bin_idx[p]];
        s += ell[i];
    }
    red[tid] = s;
    __syncthreads();
    for (int off = 128; off > 0; off >>= 1) {
        if (tid < off) red[tid] += red[tid + off];
        __syncthreads();
    }
    float m1 = red[0] * (1.0f / 4096.0f);
    __syncthreads();

    float s2 = 0.0f;
    #pragma unroll
    for (int i = 0; i < 16; i++) {
        float e = ell[i] - m1;
        e = fminf(3.0f, fmaxf(-3.0f, e));
        ell[i] = e;
        s2 += e;
    }
    red[tid] = s2;
    __syncthreads();
    for (int off = 128; off > 0; off >>= 1) {
        if (tid < off) red[tid] += red[tid + off];
        __syncthreads();
    }
    float m2 = red[0] * (1.0f / 4096.0f);

    #pragma unroll
    for (int i = 0; i < 16; i++) {
        int p = tid + 256 * i;              // p = r*64 + j
        float val = expf(0.5f * (ell[i] - m2)) * (1.0f / 4096.0f);
        int j = p & 63;
        int q = ((j & 7) << 3) | (j >> 3);  // swap(j)
        g_perm[(p & ~63) | q] = val;
    }
}

// ============================================================================
// Main kernel: 128 threads = 2 groups x 64; group g owns pair (2*blk + g),
// its own 32KB u64 plane, own named barrier. Only TWO barriers per pair:
// T1-load and T2-store touch only the thread's OWN row (r == c), so the
// only cross-thread hazards are T1 store->load and T2 store->load.
// ============================================================================
__global__ void __launch_bounds__(128, 3)
spectral_kernel(const float* __restrict__ x, float* __restrict__ y) {
    extern __shared__ u64c S[];          // 2 * NPIX u64 = 64KB

    const int tid = threadIdx.x;
    const int g = tid >> 6;              // group 0/1 (warps {0,1} / {2,3})
    const int c = tid & 63;
    u64c* Sg = S + g * NPIX;
    const int barid = g + 1;
    const int r = c;                     // row owned in the row phase

    const size_t base = ((size_t)blockIdx.x * 2 + g) * (2 * NPIX);
    const float* A = x + base;
    const float* B = A + NPIX;

    u64c v[64];

    // Load column c of both images (coalesced, streaming: read exactly once).
    #pragma unroll
    for (int i = 0; i < 64; i++)
        v[i] = PPK(__ldcs(&A[i * 64 + c]), __ldcs(&B[i * 64 + c]));

    // Forward column FFT (output slot q holds freq swap(q)).
    fft64_nat<false>(v);

    // ---- Transpose 1 (u64): column layout -> row layout.
    #pragma unroll
    for (int m = 0; m < 64; m++) {
        int s = ((m & 7) << 3) | (m >> 3);         // slot holding freq m
        Sg[m * 64 + ((c + m) & 63)] = v[s];
    }
    asm volatile("bar.sync %0, 64;" :: "r"(barid) : "memory");
    #pragma unroll
    for (int j = 0; j < 64; j++)
        v[j] = Sg[r * 64 + ((j + r) & 63)];        // own row only

    // ---- Row phase: fwd row FFT + filter + inv row FFT (registers).
    fft64_nat<false>(v);
    {
        const float4* F = (const float4*)g_perm;
        #pragma unroll
        for (int k = 0; k < 16; k++) {
            float4 f = __ldg(&F[r * 16 + k]);
            v[4 * k + 0] = PMUL(v[4 * k + 0], PPK(f.x, f.x));
            v[4 * k + 1] = PMUL(v[4 * k + 1], PPK(f.y, f.y));
            v[4 * k + 2] = PMUL(v[4 * k + 2], PPK(f.z, f.z));
            v[4 * k + 3] = PMUL(v[4 * k + 3], PPK(f.w, f.w));
        }
    }
    fft64_swapin<true>(v);   // natural j-order output

    // ---- Transpose 2 (u64): row -> column. Store touches only own row
    // (same rows this thread read in T1) -> NO barrier needed before it.
    #pragma unroll
    for (int j = 0; j < 64; j++)
        Sg[r * 64 + ((j + r) & 63)] = v[j];
    asm volatile("bar.sync %0, 64;" :: "r"(barid) : "memory");
    #pragma unroll
    for (int m = 0; m < 64; m++)
        v[m] = Sg[m * 64 + ((c + m) & 63)];

    // Inverse column FFT (natural freq-row in, swapped spatial out).
    fft64_nat<true>(v);

    float* Ya = y + base;
    float* Yb = Ya + NPIX;
    #pragma unroll
    for (int i = 0; i < 64; i++) {
        int s = ((i & 7) << 3) | (i >> 3);         // slot holding spatial row i
        __stcs(&Ya[i * 64 + c], PLO(v[s]));
        __stcs(&Yb[i * 64 + c], PHI(v[s]));
    }
}

extern "C" void kernel_launch(void* const* d_in, const int* in_sizes, int n_in,
                              void* d_out, int out_size) {
    const float* x   = (const float*)d_in[0];
    const float* g1  = (const float*)d_in[1];
    const float* raw = (const float*)d_in[2];
    const int* bidx  = (const int*)d_in[3];
    float* y = (float*)d_out;

    static bool attr_set = false;
    if (!attr_set) {
        cudaFuncSetAttribute(spectral_kernel,
                             cudaFuncAttributeMaxDynamicSharedMemorySize, SMEM_BYTES);
        attr_set = true;
    }

    build_filter_kernel<<<1, 256>>>(g1, raw, bidx);
    spectral_kernel<<<GRID, 128, SMEM_BYTES>>>(x, y);
}